// round 15
// baseline (speedup 1.0000x reference)
#include <cuda_runtime.h>
#include <cuda_fp16.h>
#include <cuda_bf16.h>
#include <cstdint>

#define Bb 256
#define Tt 256
#define Ff 511
#define Uu 512
#define G4 2048   // 4*U

// ---------------- scratch (static device globals; no allocation) ----------------
__device__ float g_xcat[Bb*Tt*Uu];                     // [B*T, U] concat(inputs, score)
__device__ float g_Xx  [Bb*Tt*G4];                     // [B*T, 4U] x @ enc_Wx (unit-interleaved cols)
__device__ __half g_ench[(size_t)Bb*Tt*Uu];            // [B, T, U] encoder outputs (fp16)
__device__ float g_h [2][Bb*Uu];                       // encoder hidden ping-pong
__device__ float g_cfin[Bb*Uu];                        // encoder final cell (enc->dec handoff)
__device__ float g_xh[2][Bb*2*Uu];                     // decoder [xin | h] concat ping-pong
// bf16-split fragment weights: [kb16][nb][lane][4 uints] = {b0_hi, b1_hi, b0_lo, b1_lo}
__device__ __align__(16) uint32_t g_Wxf[(size_t)32*256*128];   // K=512  (4MB)
__device__ __align__(16) uint32_t g_Whf[(size_t)32*256*128];   // K=512  (4MB)
__device__ __align__(16) uint32_t g_Wdf[(size_t)64*256*128];   // K=1024 (8MB)
// software grid-barrier counters (monotonic per launch; zeroed in k_init)
__device__ unsigned g_bar_e;
__device__ unsigned g_bar_d;

// ---------------- math helpers ----------------
__device__ __forceinline__ float sigf(float x){
    return __fdividef(1.f, 1.f + __expf(-x));
}
__device__ __forceinline__ float tanhf_fast(float x){
    float ax = fabsf(x);
    float t  = __expf(-2.f*ax);
    float r  = __fdividef(1.f - t, 1.f + t);
    return copysignf(r, x);
}
__device__ __forceinline__ float bf16rt(float v){
    return __bfloat162float(__float2bfloat16(v));
}
__device__ __forceinline__ uint32_t packbf2(float flo, float fhi){
    uint32_t r; asm("cvt.rn.bf16x2.f32 %0, %1, %2;" : "=r"(r) : "f"(fhi), "f"(flo));
    return r;
}
__device__ __forceinline__ void mma_bf16(float* c, const uint32_t* a, uint32_t b0, uint32_t b1){
    asm volatile(
        "mma.sync.aligned.m16n8k16.row.col.f32.bf16.bf16.f32 "
        "{%0,%1,%2,%3}, {%4,%5,%6,%7}, {%8,%9}, {%0,%1,%2,%3};"
        : "+f"(c[0]), "+f"(c[1]), "+f"(c[2]), "+f"(c[3])
        : "r"(a[0]), "r"(a[1]), "r"(a[2]), "r"(a[3]), "r"(b0), "r"(b1));
}

// ---------------- software grid barrier (release/acquire via fence + atomic) ----------------
__device__ __forceinline__ void grid_bar(unsigned* ctr, unsigned target){
    __syncthreads();
    if (threadIdx.x == 0){
        __threadfence();                   // release
        atomicAdd(ctr, 1u);
        while (*(volatile unsigned*)ctr < target) __nanosleep(40);
        __threadfence();                   // acquire
    }
    __syncthreads();
}

// ---------------- merged weight rearrange: bf16 hi/lo fragments, interleaved cols ----------------
__global__ void k_rearr_all(const float* __restrict__ eWx, const float* __restrict__ eWh,
                            const float* __restrict__ dWx, const float* __restrict__ dWh){
    int job = blockIdx.x >> 10;                       // 0..3
    int idx = (blockIdx.x & 1023)*256 + threadIdx.x;  // < 262144 = 32*256*32
    const float* W = (job == 0) ? eWx : (job == 1) ? eWh : (job == 2) ? dWx : dWh;
    uint32_t* Wf   = (job == 0) ? g_Wxf : (job == 1) ? g_Whf : g_Wdf;
    int kb_off     = (job == 3) ? 32 : 0;
    int lane = idx & 31;
    int nb   = (idx >> 5) & 255;
    int kb   = idx >> 13;                 // 0..31 (K=512 rows each)
    int np = nb*8 + (lane >> 2);          // permuted col
    int c  = (np & 3)*Uu + (np >> 2);     // original col = gate*512 + u
    int k0 = kb*16 + (lane & 3)*2;
    float v00 = W[(k0    )*G4 + c], v01 = W[(k0 + 1)*G4 + c];
    float v10 = W[(k0 + 8)*G4 + c], v11 = W[(k0 + 9)*G4 + c];
    float h00 = bf16rt(v00), h01 = bf16rt(v01);
    float h10 = bf16rt(v10), h11 = bf16rt(v11);
    uint4 v;
    v.x = packbf2(v00, v01);
    v.y = packbf2(v10, v11);
    v.z = packbf2(v00 - h00, v01 - h01);
    v.w = packbf2(v10 - h10, v11 - h11);
    *(uint4*)&Wf[(((size_t)(kb + kb_off)*256 + nb)*32 + lane)*4] = v;
}

// ---------------- K0a: build xcat = concat(inputs, score) ----------------
__global__ void k_build(const float* __restrict__ inp, const float* __restrict__ score){
    int i  = blockIdx.x*256 + threadIdx.x;
    int u  = i & (Uu-1);
    int bt = i >> 9;
    g_xcat[i] = (u < Ff) ? inp[bt*Ff + u] : score[bt >> 8];
}

// ---------------- K0b: dec_in0 = mean_t(x); zero enc h0; reset barriers ----------------
__global__ void k_init(){
    int i = blockIdx.x*256 + threadIdx.x;        // < B*U
    if (i == 0){ g_bar_e = 0; g_bar_d = 0; }
    int u = i & (Uu-1);
    int b = i >> 9;
    const float* p = &g_xcat[(b*Tt)*Uu + u];
    float s = 0.f;
    for (int t = 0; t < Tt; t++) s += p[t*Uu];
    g_xh[0][b*2*Uu + u] = s * (1.f/Tt);
    g_h[0][i] = 0.f;
}

// ---------------- bf16x3 MMA mainloop: acc = A[32 rows] @ B[64-col tile], K-chunk 32 ----------------
// pool: As = pool[0..2047] (2 bufs x 1024), Bs = pool[2048..6143] (2 bufs x 2048)
__device__ __forceinline__ void mma_main(const float* __restrict__ A, int lda,
                                         const uint32_t* __restrict__ Bf, int K,
                                         uint32_t* pool, float (&acc)[2][4],
                                         int row0, int col0){
    uint32_t* As = pool;
    uint32_t* Bs = pool + 2048;

    const int t    = threadIdx.x;
    const int lane = t & 31;
    const int wid  = t >> 5;
    const int warpM = wid & 1;
    const int warpN = wid >> 1;          // 0..3, 16 cols each
    const int NK   = K >> 5;

    const int ar = t >> 3;               // 0..31
    const int ac = (t & 7) << 2;         // 0,4,..,28
    const float* Aptr = &A[(size_t)(row0 + ar)*lda + ac];
    const int r = ar & 15, mb = ar >> 4;
    int s_idx[2];
    #pragma unroll
    for (int j = 0; j < 2; j++){
        int p  = (ac >> 1) + j;
        int kk = p >> 3;
        int kl = p & 7;
        int reg    = ((r >> 3) & 1) + ((kl >> 2) << 1);
        int lane_s = (r & 7)*4 + (kl & 3);
        s_idx[j] = ((kk*2 + mb)*32 + lane_s)*8 + reg;
    }
    const uint32_t* Bbase = Bf + (size_t)(col0 >> 3)*128;   // nb0*128

    #pragma unroll
    for (int i = 0; i < 2; i++)
        #pragma unroll
        for (int j = 0; j < 4; j++) acc[i][j] = 0.f;

    // ---- stage chunk 0 ----
    float4 Av = *(const float4*)Aptr;
    uint4  Bv[2];
    #pragma unroll
    for (int kb = 0; kb < 2; kb++)
        Bv[kb] = *(const uint4*)(Bbase + (size_t)kb*32768 + t*4);
    {
        float av[4] = {Av.x, Av.y, Av.z, Av.w};
        #pragma unroll
        for (int j = 0; j < 2; j++){
            float e0 = av[2*j], e1 = av[2*j+1];
            float h0 = bf16rt(e0), h1 = bf16rt(e1);
            As[s_idx[j]    ] = packbf2(e0, e1);
            As[s_idx[j] + 4] = packbf2(e0 - h0, e1 - h1);
        }
        #pragma unroll
        for (int kb = 0; kb < 2; kb++)
            *(uint4*)(Bs + kb*1024 + t*4) = Bv[kb];
    }
    __syncthreads();

    int cur = 0;
    for (int kc = 0; kc < NK; kc++){
        if (kc + 1 < NK){
            Av = *(const float4*)(Aptr + (kc+1)*32);
            #pragma unroll
            for (int kb = 0; kb < 2; kb++)
                Bv[kb] = *(const uint4*)(Bbase + (size_t)((kc+1)*2 + kb)*32768 + t*4);
        }
        #pragma unroll
        for (int kk = 0; kk < 2; kk++){
            uint32_t ah[4], al[4];
            const uint32_t* ab = As + cur*1024 + ((kk*2 + warpM)*32 + lane)*8;
            *(uint4*)ah = *(const uint4*)(ab);
            *(uint4*)al = *(const uint4*)(ab + 4);
            #pragma unroll
            for (int nbl = 0; nbl < 2; nbl++){
                uint4 bv = *(const uint4*)(Bs + cur*2048 + kk*1024 + ((warpN*2 + nbl)*32 + lane)*4);
                mma_bf16(acc[nbl], ah, bv.z, bv.w);   // hi * lo
                mma_bf16(acc[nbl], al, bv.x, bv.y);   // lo * hi
                mma_bf16(acc[nbl], ah, bv.x, bv.y);   // hi * hi
            }
        }
        if (kc + 1 < NK){
            float av[4] = {Av.x, Av.y, Av.z, Av.w};
            int ab2 = (cur^1)*1024;
            #pragma unroll
            for (int j = 0; j < 2; j++){
                float e0 = av[2*j], e1 = av[2*j+1];
                float h0 = bf16rt(e0), h1 = bf16rt(e1);
                As[ab2 + s_idx[j]    ] = packbf2(e0, e1);
                As[ab2 + s_idx[j] + 4] = packbf2(e0 - h0, e1 - h1);
            }
            uint32_t* bl = Bs + (cur^1)*2048;
            #pragma unroll
            for (int kb = 0; kb < 2; kb++)
                *(uint4*)(bl + kb*1024 + t*4) = Bv[kb];
        }
        __syncthreads();
        cur ^= 1;
    }
}

// ---------------- big input projection: 32x64 tiles, grid (32, 2048) ----------------
__global__ void k_gemm_xx_g(){
    __shared__ __align__(16) uint32_t pool[6144];
    float acc[2][4];
    const int row0 = blockIdx.y << 5, col0 = blockIdx.x << 6;
    mma_main(g_xcat, Uu, g_Wxf, Uu, pool, acc, row0, col0);
    const int lane = threadIdx.x & 31, wid = threadIdx.x >> 5;
    const int warpM = wid & 1, warpN = wid >> 1;
    const int gg = lane >> 2, tig = lane & 3;
    const int r0 = row0 + warpM*16 + gg;
    #pragma unroll
    for (int nbl = 0; nbl < 2; nbl++){
        int col = col0 + (warpN*2 + nbl)*8 + 2*tig;
        *(float2*)&g_Xx[(size_t)r0*G4 + col]     = make_float2(acc[nbl][0], acc[nbl][1]);
        *(float2*)&g_Xx[(size_t)(r0+8)*G4 + col] = make_float2(acc[nbl][2], acc[nbl][3]);
    }
}

#define ZS_STRIDE 68

// ---------------- persistent encoder: 256 CTAs (32x64 tiles), 1 barrier/step ----------------
__global__ __launch_bounds__(256, 2) void k_enc_all(const float* __restrict__ eb){
    __shared__ __align__(16) uint32_t pool[6144];
    const int cta = blockIdx.x;              // 0..255
    const int ctx = cta & 31, cty = cta >> 5;
    const int row0 = cty << 5, col0 = ctx << 6;
    const int th = threadIdx.x;
    const int lane = th & 31, wid = th >> 5;
    const int warpM = wid & 1, warpN = wid >> 1;
    const int gg = lane >> 2, tig = lane & 3;
    const int rl = warpM*16 + gg;
    const int erow = th >> 3, u2 = th & 7;
    const int b = row0 + erow;

    float creg[2] = {0.f, 0.f};
    unsigned tgt = 0;

    for (int t = 0; t < Tt; t++){
        const int par = t & 1;
        float acc[2][4];
        mma_main(g_h[par], Uu, g_Whf, Uu, pool, acc, row0, col0);

        float* zs = reinterpret_cast<float*>(pool);   // [32][68]
        #pragma unroll
        for (int nbl = 0; nbl < 2; nbl++){
            int c = (warpN*2 + nbl)*8 + 2*tig;
            zs[rl*ZS_STRIDE + c]     = acc[nbl][0]; zs[rl*ZS_STRIDE + c + 1]     = acc[nbl][1];
            zs[(rl+8)*ZS_STRIDE + c] = acc[nbl][2]; zs[(rl+8)*ZS_STRIDE + c + 1] = acc[nbl][3];
        }
        __syncthreads();

        const float* xxrow = &g_Xx[((size_t)b*Tt + t)*G4 + col0];
        #pragma unroll
        for (int i = 0; i < 2; i++){
            int ul = u2*2 + i;
            int ug = (ctx << 4) + ul;
            float4 z4 = *(float4*)&zs[erow*ZS_STRIDE + ul*4];
            float4 xx = *(const float4*)&xxrow[ul*4];
            float zi = z4.x + xx.x + eb[ug];
            float zf = z4.y + xx.y + eb[Uu   + ug];
            float zg = z4.z + xx.z + eb[2*Uu + ug];
            float zo = z4.w + xx.w + eb[3*Uu + ug];
            float cn = sigf(zf)*creg[i] + sigf(zi)*tanhf_fast(zg);
            float hn = sigf(zo)*tanhf_fast(cn);
            creg[i] = cn;
            g_h[par^1][b*Uu + ug] = hn;
            g_ench[((size_t)b*Tt + t)*Uu + ug] = __float2half(hn);
        }
        tgt += 256;
        grid_bar(&g_bar_e, tgt);
    }
    #pragma unroll
    for (int i = 0; i < 2; i++)
        g_cfin[b*Uu + (ctx << 4) + u2*2 + i] = creg[i];
}

// ---------------- attention body (per-CTA, one batch row) ----------------
__device__ __forceinline__ void attn_body(uint32_t* pool, int b, int p, int s,
                                          float wv, float bv, float* __restrict__ out){
    float* hs  = reinterpret_cast<float*>(pool);          // 512
    float* pr  = hs + Uu;                                 // 256
    float* red = pr + Tt;                                 // 8
    int tid = threadIdx.x;
    hs[tid]       = g_xh[p][b*2*Uu + Uu + tid];
    hs[tid + 256] = g_xh[p][b*2*Uu + Uu + tid + 256];
    __syncthreads();
    int w = tid >> 5, lane = tid & 31;
    const __half* encb = &g_ench[(size_t)b*Tt*Uu];
    for (int t = w; t < Tt; t += 8){
        const __half2* e2 = reinterpret_cast<const __half2*>(encb + t*Uu);
        float sum = 0.f;
        #pragma unroll
        for (int u = lane*8; u < Uu; u += 256){
            int h2 = u >> 1;
            float2 p0 = __half22float2(e2[h2  ]);
            float2 p1 = __half22float2(e2[h2+1]);
            float2 p2 = __half22float2(e2[h2+2]);
            float2 p3 = __half22float2(e2[h2+3]);
            sum += p0.x*hs[u  ] + p0.y*hs[u+1] + p1.x*hs[u+2] + p1.y*hs[u+3]
                 + p2.x*hs[u+4] + p2.y*hs[u+5] + p3.x*hs[u+6] + p3.y*hs[u+7];
        }
        #pragma unroll
        for (int off = 16; off; off >>= 1) sum += __shfl_xor_sync(0xffffffffu, sum, off);
        if (lane == 0) pr[t] = sum;
    }
    __syncthreads();
    float logit = pr[tid]*wv + bv;
    float m = logit;
    #pragma unroll
    for (int off = 16; off; off >>= 1) m = fmaxf(m, __shfl_xor_sync(0xffffffffu, m, off));
    if (lane == 0) red[w] = m;
    __syncthreads();
    m = red[0];
    #pragma unroll
    for (int i = 1; i < 8; i++) m = fmaxf(m, red[i]);
    float e  = __expf(logit - m);
    float sm = e;
    #pragma unroll
    for (int off = 16; off; off >>= 1) sm += __shfl_xor_sync(0xffffffffu, sm, off);
    __syncthreads();
    if (lane == 0) red[w] = sm;
    __syncthreads();
    sm = 0.f;
    #pragma unroll
    for (int i = 0; i < 8; i++) sm += red[i];
    float pv = e * __fdividef(1.f, sm);
    pr[tid] = pv;
    out[((size_t)b*Tt + s)*Tt + tid] = pv;
    __syncthreads();
    const __half2* ep = reinterpret_cast<const __half2*>(encb);
    float x0 = 0.f, x1 = 0.f;
    for (int t = 0; t < Tt; t++){
        float pt = pr[t];
        float2 ev = __half22float2(ep[t*(Uu/2) + tid]);
        x0 += pt*ev.x; x1 += pt*ev.y;
    }
    g_xh[p][b*2*Uu + tid*2    ] = x0;
    g_xh[p][b*2*Uu + tid*2 + 1] = x1;
}

// ---------------- persistent decoder: 256 CTAs; GEMM (32x64) + attention each step ----------------
__global__ __launch_bounds__(256, 2) void k_dec_all(const float* __restrict__ db,
                                                    const float* __restrict__ pw,
                                                    const float* __restrict__ pb,
                                                    float* __restrict__ out){
    __shared__ __align__(16) uint32_t pool[6144];
    const int cta = blockIdx.x;              // 0..255
    const int ctx = cta & 31, cty = cta >> 5;
    const int row0 = cty << 5, col0 = ctx << 6;
    const int th = threadIdx.x;
    const int lane = th & 31, wid = th >> 5;
    const int warpM = wid & 1, warpN = wid >> 1;
    const int gg = lane >> 2, tig = lane & 3;
    const int rl = warpM*16 + gg;
    const int erow = th >> 3, u2 = th & 7;
    const int b = row0 + erow;

    const float wv = *pw, bv = *pb;

    // prologue: h handoff (enc-final h -> dec concat) + cell regs
    {
        int i0 = (cta*256 + th)*2;
        #pragma unroll
        for (int j = 0; j < 2; j++){
            int i = i0 + j;
            int u = i & (Uu-1);
            int bb = i >> 9;
            g_xh[0][bb*2*Uu + Uu + u] = g_h[0][i];
        }
    }
    float creg[2];
    #pragma unroll
    for (int i = 0; i < 2; i++)
        creg[i] = g_cfin[b*Uu + (ctx << 4) + u2*2 + i];

    unsigned tgt = 256;
    grid_bar(&g_bar_d, tgt);                 // handoff visible everywhere

    for (int s = 0; s < Tt; s++){
        const int par = s & 1;
        float acc[2][4];
        mma_main(g_xh[par], 2*Uu, g_Wdf, 2*Uu, pool, acc, row0, col0);

        float* zs = reinterpret_cast<float*>(pool);
        #pragma unroll
        for (int nbl = 0; nbl < 2; nbl++){
            int c = (warpN*2 + nbl)*8 + 2*tig;
            zs[rl*ZS_STRIDE + c]     = acc[nbl][0]; zs[rl*ZS_STRIDE + c + 1]     = acc[nbl][1];
            zs[(rl+8)*ZS_STRIDE + c] = acc[nbl][2]; zs[(rl+8)*ZS_STRIDE + c + 1] = acc[nbl][3];
        }
        __syncthreads();
        #pragma unroll
        for (int i = 0; i < 2; i++){
            int ul = u2*2 + i;
            int ug = (ctx << 4) + ul;
            float4 z4 = *(float4*)&zs[erow*ZS_STRIDE + ul*4];
            float zi = z4.x + db[ug];
            float zf = z4.y + db[Uu   + ug];
            float zg = z4.z + db[2*Uu + ug];
            float zo = z4.w + db[3*Uu + ug];
            float cn = sigf(zf)*creg[i] + sigf(zi)*tanhf_fast(zg);
            float hn = sigf(zo)*tanhf_fast(cn);
            creg[i] = cn;
            g_xh[par^1][b*2*Uu + Uu + ug] = hn;
        }
        tgt += 256;
        grid_bar(&g_bar_d, tgt);             // h(s) visible to all

        attn_body(pool, cta, par^1, s, wv, bv, out);

        tgt += 256;
        grid_bar(&g_bar_d, tgt);             // xin(s) visible before next GEMM
    }
}

// ---------------- launch (6 nodes; #6 = k_dec_all for ncu -s 5 -c 1) ----------------
extern "C" void kernel_launch(void* const* d_in, const int* in_sizes, int n_in,
                              void* d_out, int out_size){
    const float* inputs = (const float*)d_in[0];
    const float* score  = (const float*)d_in[1];
    const float* eWx    = (const float*)d_in[2];
    const float* eWh    = (const float*)d_in[3];
    const float* eb     = (const float*)d_in[4];
    const float* dWx    = (const float*)d_in[5];
    const float* dWh    = (const float*)d_in[6];
    const float* db     = (const float*)d_in[7];
    const float* pw     = (const float*)d_in[8];
    const float* pb     = (const float*)d_in[9];
    float* out = (float*)d_out;

    k_rearr_all<<<4096, 256>>>(eWx, eWh, dWx, dWh);          // 1
    k_build<<<Bb*Tt*Uu/256, 256>>>(inputs, score);           // 2
    k_init<<<Bb*Uu/256, 256>>>();                            // 3
    k_gemm_xx_g<<<dim3(32, 2048), 256>>>();                  // 4
    k_enc_all<<<256, 256>>>(eb);                             // 5
    k_dec_all<<<256, 256>>>(db, pw, pb, out);                // 6  <- ncu captures this
}